// round 14
// baseline (speedup 1.0000x reference)
#include <cuda_runtime.h>
#include <cuda_bf16.h>
#include <cstdint>

// ---------------------------------------------------------------------------
// Problem constants
// ---------------------------------------------------------------------------
#define NFEAT   128
#define EFEAT   16
#define DDIM    300
#define DDIM2   600
#define LAYERS  3
#define NGRAPH  256
#define OUTF    128
#define BN_EPS  1e-5f

#define MAX_NODES 50000
#define MAX_EDGES 800000

// Packed-plane strides (kp = k/2, padded to multiple of 16 for cp.async)
#define KPA_NODE 64     // K=128
#define KPA_ACC  160    // K=300 (Kp=150, pad->160)
#define KPA_Y1   304    // K=600 (Kp=300, pad->304)

// B-plane buffer layout (concatenated [kp][N] segments, uint32 words)
#define BOFF_NODE 0
#define BSZ_NODE  (64 * DDIM)                 // 19200
#define BOFF_W1   BSZ_NODE
#define BSZ_W1    (150 * DDIM2)               // 90000
#define BOFF_W2   (BOFF_W1 + LAYERS * BSZ_W1) // 289200
#define BSZ_W2    (300 * DDIM)                // 90000
#define BPL_TOTAL (BOFF_W2 + LAYERS * BSZ_W2) // 559200

// ---------------------------------------------------------------------------
// Scratch (device globals; no allocations allowed)
// ---------------------------------------------------------------------------
__device__ float g_hn [MAX_NODES * DDIM];
__device__ float g_acc[MAX_NODES * DDIM];
__device__ float g_y1 [MAX_NODES * DDIM2];
__device__ float g_y2 [MAX_NODES * DDIM];
__device__ float g_sum  [DDIM2];             // zero at entry; finalize re-zeros
__device__ float g_sumsq[DDIM2];
__device__ float g_scale[DDIM2];
__device__ float g_shift[DDIM2];
__device__ float g_hg [NGRAPH * DDIM];
__device__ uint32_t g_ahi[MAX_NODES * KPA_Y1];   // packed A hi plane (max K=600)
__device__ uint32_t g_alo[MAX_NODES * KPA_Y1];
__device__ uint32_t g_bhi[BPL_TOTAL];
__device__ uint32_t g_blo[BPL_TOTAL];

// ---------------------------------------------------------------------------
// bf16 split helpers (numerics validated: rel_err 3.3e-5)
// ---------------------------------------------------------------------------
__device__ __forceinline__ uint32_t pack2(__nv_bfloat16 a, __nv_bfloat16 b)
{
    return ((uint32_t)__bfloat16_as_ushort(b) << 16) | __bfloat16_as_ushort(a);
}

__device__ __forceinline__ void split2(float x0, float x1,
                                       uint32_t& hi, uint32_t& lo)
{
    __nv_bfloat16 h0 = __float2bfloat16(x0);
    __nv_bfloat16 h1 = __float2bfloat16(x1);
    float r0 = x0 - __bfloat162float(h0);
    float r1 = x1 - __bfloat162float(h1);
    hi = pack2(h0, h1);
    lo = pack2(__float2bfloat16(r0), __float2bfloat16(r1));
}

__device__ __forceinline__ void mma_bf16(float acc[4], const uint32_t a[4],
                                         const uint32_t b[2])
{
    asm volatile(
        "mma.sync.aligned.m16n8k16.row.col.f32.bf16.bf16.f32 "
        "{%0,%1,%2,%3}, {%4,%5,%6,%7}, {%8,%9}, {%0,%1,%2,%3};"
        : "+f"(acc[0]), "+f"(acc[1]), "+f"(acc[2]), "+f"(acc[3])
        : "r"(a[0]), "r"(a[1]), "r"(a[2]), "r"(a[3]), "r"(b[0]), "r"(b[1]));
}

__device__ __forceinline__ void cp16(void* sdst, const void* gsrc, bool valid)
{
    uint32_t sa = (uint32_t)__cvta_generic_to_shared(sdst);
    int sz = valid ? 16 : 0;      // sz=0 -> 16B of zero-fill
    asm volatile("cp.async.cg.shared.global [%0], [%1], 16, %2;\n"
                 :: "r"(sa), "l"(gsrc), "r"(sz));
}

// ---------------------------------------------------------------------------
// Producer: split fp32 activations into packed hi/lo bf16 planes [M][KPA]
// ---------------------------------------------------------------------------
__global__ void split_A_kernel(const float* __restrict__ X,
                               const float* __restrict__ scale,
                               const float* __restrict__ shift, int relu,
                               uint32_t* __restrict__ hi, uint32_t* __restrict__ lo,
                               int M, int K, int KPA)
{
    int i = blockIdx.x * blockDim.x + threadIdx.x;
    int total = M * KPA;
    if (i >= total) return;
    int row = i / KPA;
    int kp  = i - row * KPA;
    int k   = 2 * kp;
    uint32_t h = 0, l = 0;
    if (k < K) {                          // K even -> k+1 < K
        float2 v = *(const float2*)(X + (size_t)row * K + k);
        if (scale) {
            v.x = fmaf(v.x, scale[k],     shift[k]);
            v.y = fmaf(v.y, scale[k + 1], shift[k + 1]);
            if (relu) { v.x = fmaxf(v.x, 0.f); v.y = fmaxf(v.y, 0.f); }
        }
        split2(v.x, v.y, h, l);
    }
    hi[i] = h; lo[i] = l;
}

// ---------------------------------------------------------------------------
// Producer: split ALL weight matrices into packed planes [kp][N] (one launch)
// ---------------------------------------------------------------------------
__global__ void split_W_kernel(const float* __restrict__ nodeW,
                               const float* __restrict__ W1,
                               const float* __restrict__ W2)
{
    int i = blockIdx.x * blockDim.x + threadIdx.x;
    if (i >= BPL_TOTAL) return;
    const float* src; int N, kp, n;
    if (i < BOFF_W1) {
        int t = i; kp = t / DDIM; n = t - kp * DDIM;
        src = nodeW; N = DDIM;
    } else if (i < BOFF_W2) {
        int j = i - BOFF_W1; int l = j / BSZ_W1; int t = j - l * BSZ_W1;
        kp = t / DDIM2; n = t - kp * DDIM2;
        src = W1 + (size_t)l * DDIM * DDIM2; N = DDIM2;
    } else {
        int j = i - BOFF_W2; int l = j / BSZ_W2; int t = j - l * BSZ_W2;
        kp = t / DDIM; n = t - kp * DDIM;
        src = W2 + (size_t)l * DDIM2 * DDIM; N = DDIM;
    }
    float f0 = src[(size_t)(2 * kp) * N + n];
    float f1 = src[(size_t)(2 * kp + 1) * N + n];
    uint32_t h, l2;
    split2(f0, f1, h, l2);
    g_bhi[i] = h; g_blo[i] = l2;
}

// ---------------------------------------------------------------------------
// bf16x3 GEMM on packed planes (unchanged from R9 — proven)
// ---------------------------------------------------------------------------
#define A_TILE_U32 (128 * 20)    // 2560
#define B_TILE_U32 (16 * 72)     // 1152
#define PK_SMEM_U32 (4 * A_TILE_U32 + 4 * B_TILE_U32 + 128)
#define PK_SMEM_BYTES (PK_SMEM_U32 * 4)      // 59904

__global__ __launch_bounds__(256)
void gemm_pk(const uint32_t* __restrict__ Ah, const uint32_t* __restrict__ Al,
             const uint32_t* __restrict__ Bh, const uint32_t* __restrict__ Bl,
             const float* __restrict__ bias,
             float* __restrict__ C, float* __restrict__ C2, int doStats,
             int M, int N, int Kp, int KPA)
{
    extern __shared__ uint32_t su[];
    uint32_t* AhS = su;
    uint32_t* AlS = su + 2 * A_TILE_U32;
    uint32_t* BhS = su + 4 * A_TILE_U32;
    uint32_t* BlS = su + 4 * A_TILE_U32 + 2 * B_TILE_U32;
    float*  cstat = (float*)(su + 4 * A_TILE_U32 + 4 * B_TILE_U32);

    const int tid  = threadIdx.x;
    const int warp = tid >> 5;
    const int lane = tid & 31;
    const int wm = warp >> 1;
    const int wn = warp & 1;
    const int r  = lane >> 2;
    const int c  = lane & 3;
    const int bm = blockIdx.y * 128;
    const int bn = blockIdx.x * 64;

    float acc[2][4][4];
#pragma unroll
    for (int mt = 0; mt < 2; mt++)
#pragma unroll
        for (int nt = 0; nt < 4; nt++)
#pragma unroll
            for (int i = 0; i < 4; i++) acc[mt][nt][i] = 0.f;

    const int T = (Kp + 15) >> 4;

    auto issue_tile = [&](int t, int sel) {
#pragma unroll
        for (int j = 0; j < 4; j++) {
            int v   = tid + 256 * j;
            int row = v >> 3;
            int q   = v & 7;
            int pl  = q >> 2;
            int qc  = q & 3;
            int kpo = t * 16 + qc * 4;
            bool val = (bm + row < M) && (kpo < KPA);
            const uint32_t* g = (pl ? Al : Ah);
            g = val ? (g + (size_t)(bm + row) * KPA + kpo) : g;
            uint32_t* s = (pl ? AlS : AhS) + sel * A_TILE_U32 + row * 20 + qc * 4;
            cp16(s, g, val);
        }
#pragma unroll
        for (int j = 0; j < 2; j++) {
            int v  = tid + 256 * j;
            int pl = v >> 8;
            int w  = v & 255;
            int kr = w >> 4;
            int nc = w & 15;
            int kpo = t * 16 + kr;
            int gn  = bn + nc * 4;
            bool val = (kpo < Kp) && (gn < N);
            const uint32_t* g = (pl ? Bl : Bh);
            g = val ? (g + (size_t)kpo * N + gn) : g;
            uint32_t* s = (pl ? BlS : BhS) + sel * B_TILE_U32 + kr * 72 + nc * 4;
            cp16(s, g, val);
        }
        asm volatile("cp.async.commit_group;\n" ::: "memory");
    };

    issue_tile(0, 0);

    for (int t = 0; t < T; t++) {
        asm volatile("cp.async.wait_group 0;\n" ::: "memory");
        __syncthreads();
        if (t + 1 < T) issue_tile(t + 1, (t + 1) & 1);

        const int s = t & 1;
        const uint32_t* As_h = AhS + s * A_TILE_U32;
        const uint32_t* As_l = AlS + s * A_TILE_U32;
        const uint32_t* Bs_h = BhS + s * B_TILE_U32;
        const uint32_t* Bs_l = BlS + s * B_TILE_U32;

#pragma unroll
        for (int ks = 0; ks < 2; ks++) {
            const int kpb = ks * 8;
            uint32_t ah[2][4], al2[2][4];
#pragma unroll
            for (int mt = 0; mt < 2; mt++) {
                int m0 = wm * 32 + mt * 16;
                int o  = (m0 + r) * 20 + kpb + c;
                ah[mt][0]  = As_h[o];       ah[mt][1]  = As_h[o + 160];
                ah[mt][2]  = As_h[o + 4];   ah[mt][3]  = As_h[o + 164];
                al2[mt][0] = As_l[o];       al2[mt][1] = As_l[o + 160];
                al2[mt][2] = As_l[o + 4];   al2[mt][3] = As_l[o + 164];
            }
            uint32_t bh[4][2], bl2[4][2];
#pragma unroll
            for (int nt = 0; nt < 4; nt++) {
                int o = (kpb + c) * 72 + wn * 32 + nt * 8 + r;
                bh[nt][0]  = Bs_h[o];  bh[nt][1]  = Bs_h[o + 4 * 72];
                bl2[nt][0] = Bs_l[o];  bl2[nt][1] = Bs_l[o + 4 * 72];
            }
#pragma unroll
            for (int mt = 0; mt < 2; mt++)
#pragma unroll
                for (int nt = 0; nt < 4; nt++) {
                    mma_bf16(acc[mt][nt], al2[mt], bh[nt]);
                    mma_bf16(acc[mt][nt], ah[mt],  bl2[nt]);
                    mma_bf16(acc[mt][nt], ah[mt],  bh[nt]);
                }
        }
        __syncthreads();
    }

    float colS[8], colQ[8];
#pragma unroll
    for (int i = 0; i < 8; i++) { colS[i] = 0.f; colQ[i] = 0.f; }

#pragma unroll
    for (int mt = 0; mt < 2; mt++) {
        int row0 = bm + wm * 32 + mt * 16 + r;
#pragma unroll
        for (int nt = 0; nt < 4; nt++) {
            int col = bn + wn * 32 + nt * 8 + 2 * c;
            if (col >= N) continue;
            float bx = bias[col], by = bias[col + 1];
            if (row0 < M) {
                float ox = acc[mt][nt][0] + bx;
                float oy = acc[mt][nt][1] + by;
                *(float2*)(C + (size_t)row0 * N + col) = make_float2(ox, oy);
                if (C2) *(float2*)(C2 + (size_t)row0 * N + col) = make_float2(ox, oy);
                colS[nt * 2 + 0] += ox; colQ[nt * 2 + 0] += ox * ox;
                colS[nt * 2 + 1] += oy; colQ[nt * 2 + 1] += oy * oy;
            }
            int row1 = row0 + 8;
            if (row1 < M) {
                float ox = acc[mt][nt][2] + bx;
                float oy = acc[mt][nt][3] + by;
                *(float2*)(C + (size_t)row1 * N + col) = make_float2(ox, oy);
                if (C2) *(float2*)(C2 + (size_t)row1 * N + col) = make_float2(ox, oy);
                colS[nt * 2 + 0] += ox; colQ[nt * 2 + 0] += ox * ox;
                colS[nt * 2 + 1] += oy; colQ[nt * 2 + 1] += oy * oy;
            }
        }
    }

    if (doStats) {
        if (tid < 128) cstat[tid] = 0.f;
        __syncthreads();
#pragma unroll
        for (int nt = 0; nt < 4; nt++) {
#pragma unroll
            for (int p = 0; p < 2; p++) {
                int lc = wn * 32 + nt * 8 + 2 * c + p;
                if (bn + lc < N) {
                    atomicAdd(&cstat[lc],      colS[nt * 2 + p]);
                    atomicAdd(&cstat[64 + lc], colQ[nt * 2 + p]);
                }
            }
        }
        __syncthreads();
        if (tid < 64) {
            int gc = bn + tid;
            if (gc < N) {
                atomicAdd(&g_sum[gc],   cstat[tid]);
                atomicAdd(&g_sumsq[gc], cstat[64 + tid]);
            }
        }
    }
}

// ---------------------------------------------------------------------------
// Scatter v4: register-pinned weights + cp.async smem staging of hn gathers.
// The R13 version staged 4 gathers in 16 registers (regs=124 -> 2 blocks/SM,
// occ 24.3%, issue 37.1%: still latency-bound). Here each thread cp.asyncs
// its 16B hn slice into a private smem slot: no destination register, depth
// goes 4 -> 6 (50% more gathers in flight), and wait_group(1) lets batch n+1
// load while batch n computes. No __syncthreads (slots are thread-private).
// Group edge lists are contiguous (30 edges) for edge_feat L1 locality.
// ---------------------------------------------------------------------------
#define SQUADS (DDIM / 4)        // 75
#define SGROUPS 3
#define EILP 6
#define EPG 30                   // edges per group
#define EPB3 (SGROUPS * EPG)     // 90 edges per block

__global__ __launch_bounds__(256, 2)
void scatter_kernel(const float* __restrict__ edge_feat,
                    const int* __restrict__ src, const int* __restrict__ dst,
                    const float* __restrict__ eW, const float* __restrict__ eb,
                    const float* __restrict__ hn, float* __restrict__ acc, int E)
{
    __shared__ __align__(16) float4 stage[2][SGROUPS * SQUADS][EILP]; // 43.2KB

    const int tid = threadIdx.x;
    const int grp = tid / SQUADS;          // 0..2 active, 3 idle
    if (grp >= SGROUPS) return;            // no __syncthreads below
    const int qd = tid - grp * SQUADS;     // 0..74
    const int d0 = qd * 4;
    const int at = grp * SQUADS + qd;      // 0..224 stage row

    // pin weights + bias in registers (once per kernel)
    float4 w[EFEAT];
#pragma unroll
    for (int k = 0; k < EFEAT; k++)
        w[k] = *(const float4*)(eW + k * DDIM + d0);
    const float4 bv = *(const float4*)(eb + d0);

    const int gstart = blockIdx.x * EPB3 + grp * EPG;
    const int gend   = min(gstart + EPG, E);
    if (gstart >= gend) return;

    auto issue = [&](int base, int buf) {
#pragma unroll
        for (int i = 0; i < EILP; i++) {
            int e = base + i;
            bool v = (e < gend);
            int se = v ? __ldg(&src[e]) : 0;
            cp16(&stage[buf][at][i], hn + (size_t)se * DDIM + d0, v);
        }
        asm volatile("cp.async.commit_group;\n" ::: "memory");
    };

    issue(gstart, 0);
    int buf = 0;

    for (int base = gstart; base < gend; base += EILP) {
        const int nbase = base + EILP;
        const bool more = (nbase < gend);
        if (more) {
            issue(nbase, buf ^ 1);
            asm volatile("cp.async.wait_group 1;\n" ::: "memory");
        } else {
            asm volatile("cp.async.wait_group 0;\n" ::: "memory");
        }

#pragma unroll
        for (int i = 0; i < EILP; i++) {
            int e = base + i;
            if (e >= gend) break;
            const int de = __ldg(&dst[e]);
            const float4 sv = stage[buf][at][i];
            const float4* ef4 = (const float4*)(edge_feat + (size_t)e * EFEAT);
            float4 f0 = ef4[0], f1 = ef4[1], f2 = ef4[2], f3 = ef4[3];
            const float efv[EFEAT] = { f0.x, f0.y, f0.z, f0.w,
                                       f1.x, f1.y, f1.z, f1.w,
                                       f2.x, f2.y, f2.z, f2.w,
                                       f3.x, f3.y, f3.z, f3.w };
            float4 h = bv;
#pragma unroll
            for (int k = 0; k < EFEAT; k++) {
                h.x = fmaf(efv[k], w[k].x, h.x);
                h.y = fmaf(efv[k], w[k].y, h.y);
                h.z = fmaf(efv[k], w[k].z, h.z);
                h.w = fmaf(efv[k], w[k].w, h.w);
            }
            float mx = fmaxf(sv.x + h.x, 0.f);
            float my = fmaxf(sv.y + h.y, 0.f);
            float mz = fmaxf(sv.z + h.z, 0.f);
            float mw = fmaxf(sv.w + h.w, 0.f);
            asm volatile("red.global.add.v4.f32 [%0], {%1,%2,%3,%4};"
                         :: "l"(acc + (size_t)de * DDIM + d0),
                            "f"(mx), "f"(my), "f"(mz), "f"(mw)
                         : "memory");
        }
        buf ^= 1;
    }
}

// ---------------------------------------------------------------------------
// BN finalize (consumes + re-zeros stats) and BN apply
// ---------------------------------------------------------------------------
__global__ void finalize_kernel(const float* __restrict__ gamma,
                                const float* __restrict__ beta, int Nc, int M)
{
    int c = threadIdx.x + blockIdx.x * blockDim.x;
    if (c >= Nc) return;
    float s = g_sum[c], ss = g_sumsq[c];
    g_sum[c] = 0.f;
    g_sumsq[c] = 0.f;
    float invM = 1.f / (float)M;
    float mean = s * invM;
    float var  = fmaxf(ss * invM - mean * mean, 0.f);
    float sc   = gamma[c] * rsqrtf(var + BN_EPS);
    g_scale[c] = sc;
    g_shift[c] = beta[c] - mean * sc;
}

__global__ void apply_bn_kernel(const float* __restrict__ Y,
                                float* __restrict__ out1, float* __restrict__ out2,
                                int relu, int total4, int Nc)
{
    int i4 = threadIdx.x + blockIdx.x * blockDim.x;
    if (i4 >= total4) return;
    size_t idx = (size_t)i4 * 4;
    int d0 = (int)(idx % Nc);
    float4 v = *(const float4*)(Y + idx);
    float4 o;
    o.x = fmaf(v.x, g_scale[d0+0], g_shift[d0+0]);
    o.y = fmaf(v.y, g_scale[d0+1], g_shift[d0+1]);
    o.z = fmaf(v.z, g_scale[d0+2], g_shift[d0+2]);
    o.w = fmaf(v.w, g_scale[d0+3], g_shift[d0+3]);
    if (relu) {
        o.x = fmaxf(o.x, 0.f); o.y = fmaxf(o.y, 0.f);
        o.z = fmaxf(o.z, 0.f); o.w = fmaxf(o.w, 0.f);
    }
    *(float4*)(out1 + idx) = o;
    if (out2) *(float4*)(out2 + idx) = o;
}

// ---------------------------------------------------------------------------
// Mean pooling + head
// ---------------------------------------------------------------------------
__device__ __forceinline__ int lower_bound_dev(const int* a, int n, int key)
{
    int lo = 0, hi = n;
    while (lo < hi) {
        int mid = (lo + hi) >> 1;
        if (a[mid] < key) lo = mid + 1; else hi = mid;
    }
    return lo;
}

__global__ void pool_kernel(const float* __restrict__ hn,
                            const int* __restrict__ gid, int Nn)
{
    __shared__ int s_lo, s_hi;
    int g = blockIdx.x;
    if (threadIdx.x == 0) {
        s_lo = lower_bound_dev(gid, Nn, g);
        s_hi = lower_bound_dev(gid, Nn, g + 1);
    }
    __syncthreads();
    int lo = s_lo, hi = s_hi;
    float inv = 1.f / fmaxf((float)(hi - lo), 1.f);
    for (int d = threadIdx.x; d < DDIM; d += blockDim.x) {
        float s = 0.f;
        for (int r = lo; r < hi; r++) s += hn[(size_t)r * DDIM + d];
        g_hg[g * DDIM + d] = s * inv;
    }
}

__global__ void pred_kernel(const float* __restrict__ W,
                            const float* __restrict__ b, float* __restrict__ out)
{
    __shared__ float h[DDIM];
    int g = blockIdx.x;
    for (int i = threadIdx.x; i < DDIM; i += blockDim.x) h[i] = g_hg[g * DDIM + i];
    __syncthreads();
    int o = threadIdx.x;
    float s = b[o];
    for (int k = 0; k < DDIM; k++)
        s = fmaf(h[k], W[k * OUTF + o], s);
    out[g * OUTF + o] = s;
}

// ---------------------------------------------------------------------------
// Launch
// ---------------------------------------------------------------------------
static inline int ceil_div(int a, int b) { return (a + b - 1) / b; }

extern "C" void kernel_launch(void* const* d_in, const int* in_sizes, int n_in,
                              void* d_out, int out_size)
{
    const float* node_feat = (const float*)d_in[0];
    const float* edge_feat = (const float*)d_in[1];
    const int*   src       = (const int*)d_in[2];
    const int*   dst       = (const int*)d_in[3];
    const int*   gid       = (const int*)d_in[4];

    int base = 5;
    if (in_sizes[5] == 1) base = 6;

    const float* node_W = (const float*)d_in[base + 0];
    const float* node_b = (const float*)d_in[base + 1];
    const float* edge_W = (const float*)d_in[base + 2];
    const float* edge_b = (const float*)d_in[base + 3];
    const float* W1     = (const float*)d_in[base + 4];
    const float* b1     = (const float*)d_in[base + 5];
    const float* g1     = (const float*)d_in[base + 6];
    const float* beta1  = (const float*)d_in[base + 7];
    const float* W2     = (const float*)d_in[base + 8];
    const float* b2     = (const float*)d_in[base + 9];
    const float* g2     = (const float*)d_in[base + 10];
    const float* beta2  = (const float*)d_in[base + 11];
    const float* pred_W = (const float*)d_in[base + 12];
    const float* pred_b = (const float*)d_in[base + 13];

    const int Nn = in_sizes[0] / NFEAT;
    const int E  = in_sizes[1] / EFEAT;

    float *hn, *acc, *y1, *y2, *scl, *shf;
    uint32_t *ahi, *alo, *bhi, *blo;
    cudaGetSymbolAddress((void**)&hn,  g_hn);
    cudaGetSymbolAddress((void**)&acc, g_acc);
    cudaGetSymbolAddress((void**)&y1,  g_y1);
    cudaGetSymbolAddress((void**)&y2,  g_y2);
    cudaGetSymbolAddress((void**)&scl, g_scale);
    cudaGetSymbolAddress((void**)&shf, g_shift);
    cudaGetSymbolAddress((void**)&ahi, g_ahi);
    cudaGetSymbolAddress((void**)&alo, g_alo);
    cudaGetSymbolAddress((void**)&bhi, g_bhi);
    cudaGetSymbolAddress((void**)&blo, g_blo);

    cudaFuncSetAttribute(gemm_pk,
                         cudaFuncAttributeMaxDynamicSharedMemorySize,
                         PK_SMEM_BYTES);

    // launch 0: split all weight matrices into packed planes
    split_W_kernel<<<ceil_div(BPL_TOTAL, 256), 256>>>(node_W, W1, W2);

    // launch 1: split node_feat
    split_A_kernel<<<ceil_div(Nn * KPA_NODE, 256), 256>>>(
        node_feat, nullptr, nullptr, 0, ahi, alo, Nn, NFEAT, KPA_NODE);

    // launch 2: node encoder GEMM -> hn (and acc)
    {
        dim3 grid(ceil_div(DDIM, 64), ceil_div(Nn, 128));
        gemm_pk<<<grid, 256, PK_SMEM_BYTES>>>(
            ahi, alo, bhi + BOFF_NODE, blo + BOFF_NODE, node_b,
            hn, acc, 0, Nn, DDIM, 64, KPA_NODE);
    }

    for (int l = 0; l < LAYERS; l++) {
        // scatter
        scatter_kernel<<<ceil_div(E, EPB3), 256>>>(
            edge_feat, src, dst,
            edge_W + (size_t)l * EFEAT * DDIM, edge_b + (size_t)l * DDIM,
            hn, acc, E);

        // split acc
        split_A_kernel<<<ceil_div(Nn * KPA_ACC, 256), 256>>>(
            acc, nullptr, nullptr, 0, ahi, alo, Nn, DDIM, KPA_ACC);

        // Linear1 GEMM y1 = acc @ W1 + b1, stats fused
        {
            dim3 grid(ceil_div(DDIM2, 64), ceil_div(Nn, 128));
            gemm_pk<<<grid, 256, PK_SMEM_BYTES>>>(
                ahi, alo, bhi + BOFF_W1 + l * BSZ_W1, blo + BOFF_W1 + l * BSZ_W1,
                b1 + (size_t)l * DDIM2, y1, nullptr, 1, Nn, DDIM2, 150, KPA_ACC);
        }
        finalize_kernel<<<1, DDIM2>>>(g1 + (size_t)l * DDIM2,
                                      beta1 + (size_t)l * DDIM2, DDIM2, Nn);

        // split y1 with fused BN1 + relu
        split_A_kernel<<<ceil_div(Nn * KPA_Y1, 256), 256>>>(
            y1, scl, shf, 1, ahi, alo, Nn, DDIM2, KPA_Y1);

        // Linear2 GEMM y2 = relu(bn1(y1)) @ W2 + b2, stats fused
        {
            dim3 grid(ceil_div(DDIM, 64), ceil_div(Nn, 128));
            gemm_pk<<<grid, 256, PK_SMEM_BYTES>>>(
                ahi, alo, bhi + BOFF_W2 + l * BSZ_W2, blo + BOFF_W2 + l * BSZ_W2,
                b2 + (size_t)l * DDIM, y2, nullptr, 1, Nn, DDIM, 300, KPA_Y1);
        }
        finalize_kernel<<<1, DDIM>>>(g2 + (size_t)l * DDIM,
                                     beta2 + (size_t)l * DDIM, DDIM, Nn);

        // hn = bn2(y2) (+relu except last); acc re-seeded for next layer
        {
            int total4 = Nn * DDIM / 4;
            int relu = (l != LAYERS - 1) ? 1 : 0;
            float* accOut = (l != LAYERS - 1) ? acc : nullptr;
            apply_bn_kernel<<<ceil_div(total4, 256), 256>>>(y2, hn, accOut,
                                                            relu, total4, DDIM);
        }
    }

    pool_kernel<<<NGRAPH, 256>>>(hn, gid, Nn);
    pred_kernel<<<NGRAPH, OUTF>>>(pred_W, pred_b, (float*)d_out);
}

// round 17
// speedup vs baseline: 1.0543x; 1.0543x over previous
#include <cuda_runtime.h>
#include <cuda_bf16.h>
#include <cstdint>

// ---------------------------------------------------------------------------
// Problem constants
// ---------------------------------------------------------------------------
#define NFEAT   128
#define EFEAT   16
#define DDIM    300
#define DDIM2   600
#define LAYERS  3
#define NGRAPH  256
#define OUTF    128
#define BN_EPS  1e-5f

#define MAX_NODES 50000
#define MAX_EDGES 800000

// Packed-plane strides (kp = k/2, padded to multiple of 16 for cp.async)
#define KPA_NODE 64     // K=128
#define KPA_ACC  160    // K=300 (Kp=150, pad->160)
#define KPA_Y1   304    // K=600 (Kp=300, pad->304)

// B-plane buffer layout (concatenated [kp][N] segments, uint32 words)
#define BOFF_NODE 0
#define BSZ_NODE  (64 * DDIM)                 // 19200
#define BOFF_W1   BSZ_NODE
#define BSZ_W1    (150 * DDIM2)               // 90000
#define BOFF_W2   (BOFF_W1 + LAYERS * BSZ_W1) // 289200
#define BSZ_W2    (300 * DDIM)                // 90000
#define BPL_TOTAL (BOFF_W2 + LAYERS * BSZ_W2) // 559200

// ---------------------------------------------------------------------------
// Scratch (device globals; no allocations allowed)
// ---------------------------------------------------------------------------
__device__ float g_hn [MAX_NODES * DDIM];
__device__ float g_acc[MAX_NODES * DDIM];
__device__ float g_y1 [MAX_NODES * DDIM2];
__device__ float g_y2 [MAX_NODES * DDIM];
__device__ float g_sum  [DDIM2];             // zero at entry; finalize re-zeros
__device__ float g_sumsq[DDIM2];
__device__ float g_scale[DDIM2];
__device__ float g_shift[DDIM2];
__device__ float g_hg [NGRAPH * DDIM];
__device__ uint32_t g_ahi[MAX_NODES * KPA_Y1];   // packed A hi plane (max K=600)
__device__ uint32_t g_alo[MAX_NODES * KPA_Y1];
__device__ uint32_t g_bhi[BPL_TOTAL];
__device__ uint32_t g_blo[BPL_TOTAL];

// ---------------------------------------------------------------------------
// bf16 split helpers (numerics validated: rel_err 3.3e-5)
// ---------------------------------------------------------------------------
__device__ __forceinline__ uint32_t pack2(__nv_bfloat16 a, __nv_bfloat16 b)
{
    return ((uint32_t)__bfloat16_as_ushort(b) << 16) | __bfloat16_as_ushort(a);
}

__device__ __forceinline__ void split2(float x0, float x1,
                                       uint32_t& hi, uint32_t& lo)
{
    __nv_bfloat16 h0 = __float2bfloat16(x0);
    __nv_bfloat16 h1 = __float2bfloat16(x1);
    float r0 = x0 - __bfloat162float(h0);
    float r1 = x1 - __bfloat162float(h1);
    hi = pack2(h0, h1);
    lo = pack2(__float2bfloat16(r0), __float2bfloat16(r1));
}

__device__ __forceinline__ void mma_bf16(float acc[4], const uint32_t a[4],
                                         const uint32_t b[2])
{
    asm volatile(
        "mma.sync.aligned.m16n8k16.row.col.f32.bf16.bf16.f32 "
        "{%0,%1,%2,%3}, {%4,%5,%6,%7}, {%8,%9}, {%0,%1,%2,%3};"
        : "+f"(acc[0]), "+f"(acc[1]), "+f"(acc[2]), "+f"(acc[3])
        : "r"(a[0]), "r"(a[1]), "r"(a[2]), "r"(a[3]), "r"(b[0]), "r"(b[1]));
}

__device__ __forceinline__ void cp16(void* sdst, const void* gsrc, bool valid)
{
    uint32_t sa = (uint32_t)__cvta_generic_to_shared(sdst);
    int sz = valid ? 16 : 0;      // sz=0 -> 16B of zero-fill
    asm volatile("cp.async.cg.shared.global [%0], [%1], 16, %2;\n"
                 :: "r"(sa), "l"(gsrc), "r"(sz));
}

// ---------------------------------------------------------------------------
// Producer: split fp32 activations into packed hi/lo bf16 planes [M][KPA]
// Vectorized: 4 kp (8 k) per thread -> uint4 stores, 2x float4 loads.
// ---------------------------------------------------------------------------
__global__ void split_A_kernel(const float* __restrict__ X,
                               const float* __restrict__ scale,
                               const float* __restrict__ shift, int relu,
                               uint32_t* __restrict__ hi, uint32_t* __restrict__ lo,
                               int M, int K, int KPA)
{
    int i4 = blockIdx.x * blockDim.x + threadIdx.x;
    int total = M * (KPA >> 2);
    if (i4 >= total) return;
    int qpr = KPA >> 2;                  // quads per row
    int row = i4 / qpr;
    int q   = i4 - row * qpr;
    int k0  = q * 8;                     // first k of the 8-wide span

    float t[8];
    if (k0 + 8 <= K) {
        float4 a = *(const float4*)(X + (size_t)row * K + k0);
        float4 b = *(const float4*)(X + (size_t)row * K + k0 + 4);
        t[0] = a.x; t[1] = a.y; t[2] = a.z; t[3] = a.w;
        t[4] = b.x; t[5] = b.y; t[6] = b.z; t[7] = b.w;
    } else {
#pragma unroll
        for (int j = 0; j < 8; j++)
            t[j] = (k0 + j < K) ? X[(size_t)row * K + k0 + j] : 0.f;
    }
    if (scale) {
#pragma unroll
        for (int j = 0; j < 8; j++) {
            int k = k0 + j;
            if (k < K) {
                float u = fmaf(t[j], scale[k], shift[k]);
                t[j] = relu ? fmaxf(u, 0.f) : u;
            }
        }
    }
    uint4 hv, lv;
    split2(t[0], t[1], hv.x, lv.x);
    split2(t[2], t[3], hv.y, lv.y);
    split2(t[4], t[5], hv.z, lv.z);
    split2(t[6], t[7], hv.w, lv.w);
    size_t o = (size_t)row * KPA + q * 4;
    *(uint4*)(hi + o) = hv;
    *(uint4*)(lo + o) = lv;
}

// ---------------------------------------------------------------------------
// Producer: split ALL weight matrices into packed planes [kp][N] (one launch)
// ---------------------------------------------------------------------------
__global__ void split_W_kernel(const float* __restrict__ nodeW,
                               const float* __restrict__ W1,
                               const float* __restrict__ W2)
{
    int i = blockIdx.x * blockDim.x + threadIdx.x;
    if (i >= BPL_TOTAL) return;
    const float* src; int N, kp, n;
    if (i < BOFF_W1) {
        int t = i; kp = t / DDIM; n = t - kp * DDIM;
        src = nodeW; N = DDIM;
    } else if (i < BOFF_W2) {
        int j = i - BOFF_W1; int l = j / BSZ_W1; int t = j - l * BSZ_W1;
        kp = t / DDIM2; n = t - kp * DDIM2;
        src = W1 + (size_t)l * DDIM * DDIM2; N = DDIM2;
    } else {
        int j = i - BOFF_W2; int l = j / BSZ_W2; int t = j - l * BSZ_W2;
        kp = t / DDIM; n = t - kp * DDIM;
        src = W2 + (size_t)l * DDIM2 * DDIM; N = DDIM;
    }
    float f0 = src[(size_t)(2 * kp) * N + n];
    float f1 = src[(size_t)(2 * kp + 1) * N + n];
    uint32_t h, l2;
    split2(f0, f1, h, l2);
    g_bhi[i] = h; g_blo[i] = l2;
}

// ---------------------------------------------------------------------------
// bf16x3 GEMM on packed planes (R9-proven compute; launch_bounds(256,3)
// experiment: cap regs ~84 so 3 blocks/SM = 24 warps, testing whether the
// fallback-HMMA pipe is latency-bound at 16 warps)
// ---------------------------------------------------------------------------
#define A_TILE_U32 (128 * 20)    // 2560
#define B_TILE_U32 (16 * 72)     // 1152
#define PK_SMEM_U32 (4 * A_TILE_U32 + 4 * B_TILE_U32 + 128)
#define PK_SMEM_BYTES (PK_SMEM_U32 * 4)      // 59904

__global__ __launch_bounds__(256, 3)
void gemm_pk(const uint32_t* __restrict__ Ah, const uint32_t* __restrict__ Al,
             const uint32_t* __restrict__ Bh, const uint32_t* __restrict__ Bl,
             const float* __restrict__ bias,
             float* __restrict__ C, float* __restrict__ C2, int doStats,
             int M, int N, int Kp, int KPA)
{
    extern __shared__ uint32_t su[];
    uint32_t* AhS = su;
    uint32_t* AlS = su + 2 * A_TILE_U32;
    uint32_t* BhS = su + 4 * A_TILE_U32;
    uint32_t* BlS = su + 4 * A_TILE_U32 + 2 * B_TILE_U32;
    float*  cstat = (float*)(su + 4 * A_TILE_U32 + 4 * B_TILE_U32);

    const int tid  = threadIdx.x;
    const int warp = tid >> 5;
    const int lane = tid & 31;
    const int wm = warp >> 1;
    const int wn = warp & 1;
    const int r  = lane >> 2;
    const int c  = lane & 3;
    const int bm = blockIdx.y * 128;
    const int bn = blockIdx.x * 64;

    float acc[2][4][4];
#pragma unroll
    for (int mt = 0; mt < 2; mt++)
#pragma unroll
        for (int nt = 0; nt < 4; nt++)
#pragma unroll
            for (int i = 0; i < 4; i++) acc[mt][nt][i] = 0.f;

    const int T = (Kp + 15) >> 4;

    auto issue_tile = [&](int t, int sel) {
#pragma unroll
        for (int j = 0; j < 4; j++) {
            int v   = tid + 256 * j;
            int row = v >> 3;
            int q   = v & 7;
            int pl  = q >> 2;
            int qc  = q & 3;
            int kpo = t * 16 + qc * 4;
            bool val = (bm + row < M) && (kpo < KPA);
            const uint32_t* g = (pl ? Al : Ah);
            g = val ? (g + (size_t)(bm + row) * KPA + kpo) : g;
            uint32_t* s = (pl ? AlS : AhS) + sel * A_TILE_U32 + row * 20 + qc * 4;
            cp16(s, g, val);
        }
#pragma unroll
        for (int j = 0; j < 2; j++) {
            int v  = tid + 256 * j;
            int pl = v >> 8;
            int w  = v & 255;
            int kr = w >> 4;
            int nc = w & 15;
            int kpo = t * 16 + kr;
            int gn  = bn + nc * 4;
            bool val = (kpo < Kp) && (gn < N);
            const uint32_t* g = (pl ? Bl : Bh);
            g = val ? (g + (size_t)kpo * N + gn) : g;
            uint32_t* s = (pl ? BlS : BhS) + sel * B_TILE_U32 + kr * 72 + nc * 4;
            cp16(s, g, val);
        }
        asm volatile("cp.async.commit_group;\n" ::: "memory");
    };

    issue_tile(0, 0);

    for (int t = 0; t < T; t++) {
        asm volatile("cp.async.wait_group 0;\n" ::: "memory");
        __syncthreads();
        if (t + 1 < T) issue_tile(t + 1, (t + 1) & 1);

        const int s = t & 1;
        const uint32_t* As_h = AhS + s * A_TILE_U32;
        const uint32_t* As_l = AlS + s * A_TILE_U32;
        const uint32_t* Bs_h = BhS + s * B_TILE_U32;
        const uint32_t* Bs_l = BlS + s * B_TILE_U32;

#pragma unroll
        for (int ks = 0; ks < 2; ks++) {
            const int kpb = ks * 8;
            uint32_t ah[2][4], al2[2][4];
#pragma unroll
            for (int mt = 0; mt < 2; mt++) {
                int m0 = wm * 32 + mt * 16;
                int o  = (m0 + r) * 20 + kpb + c;
                ah[mt][0]  = As_h[o];       ah[mt][1]  = As_h[o + 160];
                ah[mt][2]  = As_h[o + 4];   ah[mt][3]  = As_h[o + 164];
                al2[mt][0] = As_l[o];       al2[mt][1] = As_l[o + 160];
                al2[mt][2] = As_l[o + 4];   al2[mt][3] = As_l[o + 164];
            }
            uint32_t bh[4][2], bl2[4][2];
#pragma unroll
            for (int nt = 0; nt < 4; nt++) {
                int o = (kpb + c) * 72 + wn * 32 + nt * 8 + r;
                bh[nt][0]  = Bs_h[o];  bh[nt][1]  = Bs_h[o + 4 * 72];
                bl2[nt][0] = Bs_l[o];  bl2[nt][1] = Bs_l[o + 4 * 72];
            }
#pragma unroll
            for (int mt = 0; mt < 2; mt++)
#pragma unroll
                for (int nt = 0; nt < 4; nt++) {
                    mma_bf16(acc[mt][nt], al2[mt], bh[nt]);
                    mma_bf16(acc[mt][nt], ah[mt],  bl2[nt]);
                    mma_bf16(acc[mt][nt], ah[mt],  bh[nt]);
                }
        }
        __syncthreads();
    }

    float colS[8], colQ[8];
#pragma unroll
    for (int i = 0; i < 8; i++) { colS[i] = 0.f; colQ[i] = 0.f; }

#pragma unroll
    for (int mt = 0; mt < 2; mt++) {
        int row0 = bm + wm * 32 + mt * 16 + r;
#pragma unroll
        for (int nt = 0; nt < 4; nt++) {
            int col = bn + wn * 32 + nt * 8 + 2 * c;
            if (col >= N) continue;
            float bx = bias[col], by = bias[col + 1];
            if (row0 < M) {
                float ox = acc[mt][nt][0] + bx;
                float oy = acc[mt][nt][1] + by;
                *(float2*)(C + (size_t)row0 * N + col) = make_float2(ox, oy);
                if (C2) *(float2*)(C2 + (size_t)row0 * N + col) = make_float2(ox, oy);
                colS[nt * 2 + 0] += ox; colQ[nt * 2 + 0] += ox * ox;
                colS[nt * 2 + 1] += oy; colQ[nt * 2 + 1] += oy * oy;
            }
            int row1 = row0 + 8;
            if (row1 < M) {
                float ox = acc[mt][nt][2] + bx;
                float oy = acc[mt][nt][3] + by;
                *(float2*)(C + (size_t)row1 * N + col) = make_float2(ox, oy);
                if (C2) *(float2*)(C2 + (size_t)row1 * N + col) = make_float2(ox, oy);
                colS[nt * 2 + 0] += ox; colQ[nt * 2 + 0] += ox * ox;
                colS[nt * 2 + 1] += oy; colQ[nt * 2 + 1] += oy * oy;
            }
        }
    }

    if (doStats) {
        if (tid < 128) cstat[tid] = 0.f;
        __syncthreads();
#pragma unroll
        for (int nt = 0; nt < 4; nt++) {
#pragma unroll
            for (int p = 0; p < 2; p++) {
                int lc = wn * 32 + nt * 8 + 2 * c + p;
                if (bn + lc < N) {
                    atomicAdd(&cstat[lc],      colS[nt * 2 + p]);
                    atomicAdd(&cstat[64 + lc], colQ[nt * 2 + p]);
                }
            }
        }
        __syncthreads();
        if (tid < 64) {
            int gc = bn + tid;
            if (gc < N) {
                atomicAdd(&g_sum[gc],   cstat[tid]);
                atomicAdd(&g_sumsq[gc], cstat[64 + tid]);
            }
        }
    }
}

// ---------------------------------------------------------------------------
// Scatter (R13-proven, best measured: 498us/layer): thread-per-output-column,
// register-pinned weights, EILP=4 register-staged edge pipeline.
// ---------------------------------------------------------------------------
#define SQUADS (DDIM / 4)        // 75
#define SGROUPS 3
#define EILP 4
#define EPB3 (SGROUPS * EILP * 8)   // 96 edges per block

__global__ __launch_bounds__(256, 2)
void scatter_kernel(const float* __restrict__ edge_feat,
                    const int* __restrict__ src, const int* __restrict__ dst,
                    const float* __restrict__ eW, const float* __restrict__ eb,
                    const float* __restrict__ hn, float* __restrict__ acc, int E)
{
    const int tid = threadIdx.x;
    const int grp = tid / SQUADS;          // 0..2 active, 3 idle
    if (grp >= SGROUPS) return;            // no __syncthreads below
    const int qd = tid - grp * SQUADS;     // 0..74
    const int d0 = qd * 4;

    // pin weights + bias in registers (once per kernel)
    float4 w[EFEAT];
#pragma unroll
    for (int k = 0; k < EFEAT; k++)
        w[k] = *(const float4*)(eW + k * DDIM + d0);
    const float4 bv = *(const float4*)(eb + d0);

    const int e0   = blockIdx.x * EPB3;
    const int eEnd = min(e0 + EPB3, E);

    for (int base = e0 + grp * EILP; base < eEnd; base += SGROUPS * EILP) {
        // ---- stage: 4 independent index loads + 4 independent gathers ----
        int   de[EILP];
        float4 sv[EILP];
        bool  v[EILP];
#pragma unroll
        for (int i = 0; i < EILP; i++) {
            int e = base + i;
            v[i] = (e < eEnd);
            int se = 0;
            de[i] = 0;
            if (v[i]) { se = __ldg(&src[e]); de[i] = __ldg(&dst[e]); }
            sv[i] = v[i] ? *(const float4*)(hn + (size_t)se * DDIM + d0)
                         : make_float4(0.f, 0.f, 0.f, 0.f);
        }
        // ---- process the 4 staged edges ----
#pragma unroll
        for (int i = 0; i < EILP; i++) {
            if (!v[i]) continue;
            int e = base + i;
            const float4* ef4 = (const float4*)(edge_feat + (size_t)e * EFEAT);
            float4 f0 = ef4[0], f1 = ef4[1], f2 = ef4[2], f3 = ef4[3];
            const float efv[EFEAT] = { f0.x, f0.y, f0.z, f0.w,
                                       f1.x, f1.y, f1.z, f1.w,
                                       f2.x, f2.y, f2.z, f2.w,
                                       f3.x, f3.y, f3.z, f3.w };
            float4 h = bv;
#pragma unroll
            for (int k = 0; k < EFEAT; k++) {
                h.x = fmaf(efv[k], w[k].x, h.x);
                h.y = fmaf(efv[k], w[k].y, h.y);
                h.z = fmaf(efv[k], w[k].z, h.z);
                h.w = fmaf(efv[k], w[k].w, h.w);
            }
            float mx = fmaxf(sv[i].x + h.x, 0.f);
            float my = fmaxf(sv[i].y + h.y, 0.f);
            float mz = fmaxf(sv[i].z + h.z, 0.f);
            float mw = fmaxf(sv[i].w + h.w, 0.f);
            asm volatile("red.global.add.v4.f32 [%0], {%1,%2,%3,%4};"
                         :: "l"(acc + (size_t)de[i] * DDIM + d0),
                            "f"(mx), "f"(my), "f"(mz), "f"(mw)
                         : "memory");
        }
    }
}

// ---------------------------------------------------------------------------
// BN finalize (consumes + re-zeros stats) and BN apply
// ---------------------------------------------------------------------------
__global__ void finalize_kernel(const float* __restrict__ gamma,
                                const float* __restrict__ beta, int Nc, int M)
{
    int c = threadIdx.x + blockIdx.x * blockDim.x;
    if (c >= Nc) return;
    float s = g_sum[c], ss = g_sumsq[c];
    g_sum[c] = 0.f;
    g_sumsq[c] = 0.f;
    float invM = 1.f / (float)M;
    float mean = s * invM;
    float var  = fmaxf(ss * invM - mean * mean, 0.f);
    float sc   = gamma[c] * rsqrtf(var + BN_EPS);
    g_scale[c] = sc;
    g_shift[c] = beta[c] - mean * sc;
}

__global__ void apply_bn_kernel(const float* __restrict__ Y,
                                float* __restrict__ out1, float* __restrict__ out2,
                                int relu, int total4, int Nc)
{
    int i4 = threadIdx.x + blockIdx.x * blockDim.x;
    if (i4 >= total4) return;
    size_t idx = (size_t)i4 * 4;
    int d0 = (int)(idx % Nc);
    float4 v = *(const float4*)(Y + idx);
    float4 o;
    o.x = fmaf(v.x, g_scale[d0+0], g_shift[d0+0]);
    o.y = fmaf(v.y, g_scale[d0+1], g_shift[d0+1]);
    o.z = fmaf(v.z, g_scale[d0+2], g_shift[d0+2]);
    o.w = fmaf(v.w, g_scale[d0+3], g_shift[d0+3]);
    if (relu) {
        o.x = fmaxf(o.x, 0.f); o.y = fmaxf(o.y, 0.f);
        o.z = fmaxf(o.z, 0.f); o.w = fmaxf(o.w, 0.f);
    }
    *(float4*)(out1 + idx) = o;
    if (out2) *(float4*)(out2 + idx) = o;
}

// ---------------------------------------------------------------------------
// Mean pooling + head
// ---------------------------------------------------------------------------
__device__ __forceinline__ int lower_bound_dev(const int* a, int n, int key)
{
    int lo = 0, hi = n;
    while (lo < hi) {
        int mid = (lo + hi) >> 1;
        if (a[mid] < key) lo = mid + 1; else hi = mid;
    }
    return lo;
}

__global__ void pool_kernel(const float* __restrict__ hn,
                            const int* __restrict__ gid, int Nn)
{
    __shared__ int s_lo, s_hi;
    int g = blockIdx.x;
    if (threadIdx.x == 0) {
        s_lo = lower_bound_dev(gid, Nn, g);
        s_hi = lower_bound_dev(gid, Nn, g + 1);
    }
    __syncthreads();
    int lo = s_lo, hi = s_hi;
    float inv = 1.f / fmaxf((float)(hi - lo), 1.f);
    for (int d = threadIdx.x; d < DDIM; d += blockDim.x) {
        float s = 0.f;
        for (int r = lo; r < hi; r++) s += hn[(size_t)r * DDIM + d];
        g_hg[g * DDIM + d] = s * inv;
    }
}

__global__ void pred_kernel(const float* __restrict__ W,
                            const float* __restrict__ b, float* __restrict__ out)
{
    __shared__ float h[DDIM];
    int g = blockIdx.x;
    for (int i = threadIdx.x; i < DDIM; i += blockDim.x) h[i] = g_hg[g * DDIM + i];
    __syncthreads();
    int o = threadIdx.x;
    float s = b[o];
    for (int k = 0; k < DDIM; k++)
        s = fmaf(h[k], W[k * OUTF + o], s);
    out[g * OUTF + o] = s;
}

// ---------------------------------------------------------------------------
// Launch
// ---------------------------------------------------------------------------
static inline int ceil_div(int a, int b) { return (a + b - 1) / b; }

extern "C" void kernel_launch(void* const* d_in, const int* in_sizes, int n_in,
                              void* d_out, int out_size)
{
    const float* node_feat = (const float*)d_in[0];
    const float* edge_feat = (const float*)d_in[1];
    const int*   src       = (const int*)d_in[2];
    const int*   dst       = (const int*)d_in[3];
    const int*   gid       = (const int*)d_in[4];

    int base = 5;
    if (in_sizes[5] == 1) base = 6;

    const float* node_W = (const float*)d_in[base + 0];
    const float* node_b = (const float*)d_in[base + 1];
    const float* edge_W = (const float*)d_in[base + 2];
    const float* edge_b = (const float*)d_in[base + 3];
    const float* W1     = (const float*)d_in[base + 4];
    const float* b1     = (const float*)d_in[base + 5];
    const float* g1     = (const float*)d_in[base + 6];
    const float* beta1  = (const float*)d_in[base + 7];
    const float* W2     = (const float*)d_in[base + 8];
    const float* b2     = (const float*)d_in[base + 9];
    const float* g2     = (const float*)d_in[base + 10];
    const float* beta2  = (const float*)d_in[base + 11];
    const float* pred_W = (const float*)d_in[base + 12];
    const float* pred_b = (const float*)d_in[base + 13];

    const int Nn = in_sizes[0] / NFEAT;
    const int E  = in_sizes[1] / EFEAT;

    float *hn, *acc, *y1, *y2, *scl, *shf;
    uint32_t *ahi, *alo, *bhi, *blo;
    cudaGetSymbolAddress((void**)&hn,  g_hn);
    cudaGetSymbolAddress((void**)&acc, g_acc);
    cudaGetSymbolAddress((void**)&y1,  g_y1);
    cudaGetSymbolAddress((void**)&y2,  g_y2);
    cudaGetSymbolAddress((void**)&scl, g_scale);
    cudaGetSymbolAddress((void**)&shf, g_shift);
    cudaGetSymbolAddress((void**)&ahi, g_ahi);
    cudaGetSymbolAddress((void**)&alo, g_alo);
    cudaGetSymbolAddress((void**)&bhi, g_bhi);
    cudaGetSymbolAddress((void**)&blo, g_blo);

    cudaFuncSetAttribute(gemm_pk,
                         cudaFuncAttributeMaxDynamicSharedMemorySize,
                         PK_SMEM_BYTES);

    // launch 0: split all weight matrices into packed planes
    split_W_kernel<<<ceil_div(BPL_TOTAL, 256), 256>>>(node_W, W1, W2);

    // launch 1: split node_feat
    split_A_kernel<<<ceil_div(Nn * KPA_NODE / 4, 256), 256>>>(
        node_feat, nullptr, nullptr, 0, ahi, alo, Nn, NFEAT, KPA_NODE);

    // launch 2: node encoder GEMM -> hn (and acc)
    {
        dim3 grid(ceil_div(DDIM, 64), ceil_div(Nn, 128));
        gemm_pk<<<grid, 256, PK_SMEM_BYTES>>>(
            ahi, alo, bhi + BOFF_NODE, blo + BOFF_NODE, node_b,
            hn, acc, 0, Nn, DDIM, 64, KPA_NODE);
    }

    for (int l = 0; l < LAYERS; l++) {
        // scatter
        scatter_kernel<<<ceil_div(E, EPB3), 256>>>(
            edge_feat, src, dst,
            edge_W + (size_t)l * EFEAT * DDIM, edge_b + (size_t)l * DDIM,
            hn, acc, E);

        // split acc
        split_A_kernel<<<ceil_div(Nn * KPA_ACC / 4, 256), 256>>>(
            acc, nullptr, nullptr, 0, ahi, alo, Nn, DDIM, KPA_ACC);

        // Linear1 GEMM y1 = acc @ W1 + b1, stats fused
        {
            dim3 grid(ceil_div(DDIM2, 64), ceil_div(Nn, 128));
            gemm_pk<<<grid, 256, PK_SMEM_BYTES>>>(
                ahi, alo, bhi + BOFF_W1 + l * BSZ_W1, blo + BOFF_W1 + l * BSZ_W1,
                b1 + (size_t)l * DDIM2, y1, nullptr, 1, Nn, DDIM2, 150, KPA_ACC);
        }
        finalize_kernel<<<1, DDIM2>>>(g1 + (size_t)l * DDIM2,
                                      beta1 + (size_t)l * DDIM2, DDIM2, Nn);

        // split y1 with fused BN1 + relu
        split_A_kernel<<<ceil_div(Nn * KPA_Y1 / 4, 256), 256>>>(
            y1, scl, shf, 1, ahi, alo, Nn, DDIM2, KPA_Y1);

        // Linear2 GEMM y2 = relu(bn1(y1)) @ W2 + b2, stats fused
        {
            dim3 grid(ceil_div(DDIM, 64), ceil_div(Nn, 128));
            gemm_pk<<<grid, 256, PK_SMEM_BYTES>>>(
                ahi, alo, bhi + BOFF_W2 + l * BSZ_W2, blo + BOFF_W2 + l * BSZ_W2,
                b2 + (size_t)l * DDIM, y2, nullptr, 1, Nn, DDIM, 300, KPA_Y1);
        }
        finalize_kernel<<<1, DDIM>>>(g2 + (size_t)l * DDIM,
                                     beta2 + (size_t)l * DDIM, DDIM, Nn);

        // hn = bn2(y2) (+relu except last); acc re-seeded for next layer
        {
            int total4 = Nn * DDIM / 4;
            int relu = (l != LAYERS - 1) ? 1 : 0;
            float* accOut = (l != LAYERS - 1) ? acc : nullptr;
            apply_bn_kernel<<<ceil_div(total4, 256), 256>>>(y2, hn, accOut,
                                                            relu, total4, DDIM);
        }
    }

    pool_kernel<<<NGRAPH, 256>>>(hn, gid, Nn);
    pred_kernel<<<NGRAPH, OUTF>>>(pred_W, pred_b, (float*)d_out);
}